// round 16
// baseline (speedup 1.0000x reference)
#include <cuda_runtime.h>
#include <cuda_fp16.h>
#include <cstdint>

#define BB  4
#define QQ  512
#define MM  512
#define PPQ 128
#define HID 1024
#define HH  16
#define SS  64
#define RR  1024
#define RP  1536
#define QT  16
#define NHDIM (BB*HH)

// ---------------- global scratch (halves pre-split hi/lo) ----------------
__device__ __align__(16) __half g_ctxH[BB*RR*HID],  g_ctxL[BB*RR*HID];
__device__ __align__(16) __half g_posH[BB*RP*HID],  g_posL[BB*RP*HID];
__device__ __align__(16) __half g_conH[BB*QQ*HID],  g_conL[BB*QQ*HID];
__device__ __align__(16) __half g_qryH[BB*PPQ*HID], g_qryL[BB*PPQ*HID];
__device__ __align__(16) __half g_wH[5*HID*HID],    g_wL[5*HID*HID];   // transposed [n][k-pairs]
__device__ __align__(16) __half g_kcH[BB*RR*HID],   g_kcL[BB*RR*HID];  // [nh][r][64]
__device__ __align__(16) __half g_kpH[BB*RP*HID],   g_kpL[BB*RP*HID];  // [nh][p][64]
__device__ __align__(16) __half g_vtH[BB*RR*HID],   g_vtL[BB*RR*HID];  // [nh][s][r-pairs]
__device__ __align__(16) __half g_acH[BB*QQ*HID],   g_acL[BB*QQ*HID];
__device__ __align__(16) __half g_aqH[BB*PPQ*HID],  g_aqL[BB*PPQ*HID];
__device__ float g_v [BB*RR*HID];
__device__ float g_qc[BB*QQ*HID];
__device__ float g_qq[BB*PPQ*HID];
__device__ int   g_tpos[BB*PPQ];

// ---------------- helpers ----------------
__device__ __forceinline__ uint32_t smem_u32(const void* p){
    uint32_t a;
    asm("{ .reg .u64 t; cvta.to.shared.u64 t, %1; cvt.u32.u64 %0, t; }" : "=r"(a) : "l"(p));
    return a;
}
__device__ __forceinline__ void cpasync16(uint32_t s, const void* g){
    asm volatile("cp.async.cg.shared.global [%0], [%1], 16;" :: "r"(s), "l"(g));
}
__device__ __forceinline__ void cpcommit(){ asm volatile("cp.async.commit_group;" ::: "memory"); }
template<int N> __device__ __forceinline__ void cpwait(){ asm volatile("cp.async.wait_group %0;" :: "n"(N) : "memory"); }

__device__ __forceinline__ void ldsm4(uint32_t* r, uint32_t addr){
    asm volatile("ldmatrix.sync.aligned.m8n8.x4.shared.b16 {%0,%1,%2,%3}, [%4];"
        : "=r"(r[0]),"=r"(r[1]),"=r"(r[2]),"=r"(r[3]) : "r"(addr));
}
__device__ __forceinline__ void ldsm2(uint32_t* r, uint32_t addr){
    asm volatile("ldmatrix.sync.aligned.m8n8.x2.shared.b16 {%0,%1}, [%2];"
        : "=r"(r[0]),"=r"(r[1]) : "r"(addr));
}

__device__ __forceinline__ void split_h(float x, __half& h, __half& l){
    h = __float2half_rn(x);
    l = __float2half_rn(x - __half2float(h));
}
__device__ __forceinline__ uint32_t pack2(float a, float b, bool lo){
    __half ha, la, hb, lb;
    split_h(a, ha, la); split_h(b, hb, lb);
    __half2 v = lo ? __halves2half2(la, lb) : __halves2half2(ha, hb);
    return *(uint32_t*)&v;
}
__device__ __forceinline__ void mma_h(float* c, const uint32_t* a, const uint32_t* b){
    asm volatile("mma.sync.aligned.m16n8k16.row.col.f32.f16.f16.f32 "
        "{%0,%1,%2,%3}, {%4,%5,%6,%7}, {%8,%9}, {%0,%1,%2,%3};"
        : "+f"(c[0]),"+f"(c[1]),"+f"(c[2]),"+f"(c[3])
        : "r"(a[0]),"r"(a[1]),"r"(a[2]),"r"(a[3]), "r"(b[0]),"r"(b[1]));
}
__device__ __forceinline__ void mma3h(float* c, const uint32_t* aH, const uint32_t* aL,
                                      const uint32_t* bH, const uint32_t* bL){
    mma_h(c, aH, bH);
    mma_h(c, aH, bL);
    mma_h(c, aL, bH);
}

// ---------------- converts ----------------
__global__ void build_ctx_split(const float* __restrict__ mems, const float* __restrict__ content)
{
    int idx = blockIdx.x * blockDim.x + threadIdx.x;
    const int total = BB*RR*HID/4;
    if (idx >= total) return;
    int d4  = idx & 255;
    int row = idx >> 8;
    int n = row >> 10, r = row & 1023;
    const float* src = (r < MM) ? (mems + ((size_t)n*MM + r)*HID)
                                : (content + ((size_t)n*QQ + (r-MM))*HID);
    float4 v = ((const float4*)src)[d4];
    uint32_t* wh = (uint32_t*)g_ctxH;
    uint32_t* wl = (uint32_t*)g_ctxL;
    wh[idx*2]   = pack2(v.x, v.y, false);
    wh[idx*2+1] = pack2(v.z, v.w, false);
    wl[idx*2]   = pack2(v.x, v.y, true);
    wl[idx*2+1] = pack2(v.z, v.w, true);
}

__global__ void split_k(const float* __restrict__ src, __half* dstH, __half* dstL, int n4)
{
    int idx = blockIdx.x * blockDim.x + threadIdx.x;
    if (idx >= n4) return;
    float4 v = ((const float4*)src)[idx];
    ((uint32_t*)dstH)[idx*2]   = pack2(v.x, v.y, false);
    ((uint32_t*)dstH)[idx*2+1] = pack2(v.z, v.w, false);
    ((uint32_t*)dstL)[idx*2]   = pack2(v.x, v.y, true);
    ((uint32_t*)dstL)[idx*2+1] = pack2(v.z, v.w, true);
}

// W [k][n] -> WT halves [n][k-pairs]
__global__ void wtrans(const float* __restrict__ W, __half* dstH, __half* dstL)
{
    __shared__ float sm[32][33];
    int n0 = blockIdx.x*32, k0 = blockIdx.y*32;
    int tx = threadIdx.x, ty = threadIdx.y;
#pragma unroll
    for (int i = 0; i < 4; i++)
        sm[ty + 8*i][tx] = W[(size_t)(k0 + ty + 8*i)*1024 + n0 + tx];
    __syncthreads();
    int tid = ty*32 + tx;
    int w = tid & 15;
#pragma unroll
    for (int p = 0; p < 2; p++) {
        int nn = p*16 + (tid >> 4);
        float a = sm[2*w][nn], b = sm[2*w+1][nn];
        size_t o = (size_t)(n0 + nn)*512 + (k0 >> 1) + w;
        ((uint32_t*)dstH)[o] = pack2(a, b, false);
        ((uint32_t*)dstL)[o] = pack2(a, b, true);
    }
}

// g_v fp32 [nh][r][64] -> vt halves [nh][s][r-pairs]
__global__ void vtrans()
{
    __shared__ float vs[128][65];
    int nh = blockIdx.x >> 3, rc = blockIdx.x & 7;
    int tid = threadIdx.x;
    const float* src = g_v + ((size_t)nh*1024 + rc*128)*64;
#pragma unroll
    for (int i = 0; i < 8; i++) {
        int idx = tid + i*256;
        int r = idx >> 4, f4 = idx & 15;
        float4 v = ((const float4*)(src + (size_t)r*64))[f4];
        vs[r][f4*4] = v.x; vs[r][f4*4+1] = v.y; vs[r][f4*4+2] = v.z; vs[r][f4*4+3] = v.w;
    }
    __syncthreads();
#pragma unroll
    for (int i = 0; i < 16; i++) {
        int idx = tid + i*256;
        int s = idx >> 6, w = idx & 63;
        float a = vs[2*w][s], b = vs[2*w+1][s];
        size_t o = ((size_t)nh*64 + s)*512 + rc*64 + w;
        ((uint32_t*)g_vtH)[o] = pack2(a, b, false);
        ((uint32_t*)g_vtL)[o] = pack2(a, b, true);
    }
}

__global__ void find_tpos(const float* __restrict__ tm)
{
    int i = threadIdx.x;
    const float* row = tm + (size_t)i * QQ;
    int q = 0;
    for (int j = 0; j < QQ; j++) if (row[j] > 0.5f) q = j;
    g_tpos[i] = q;
}

// ---------------- half-split GEMM, cp.async 3-stage, ldmatrix frags ----------------
#define GPW 12
#define G_AH 0
#define G_AL (3*128*GPW)
#define G_BH (2*3*128*GPW)
#define G_BL (3*3*128*GPW)
#define GEMM_SMEM (4*3*128*GPW*4)

__global__ __launch_bounds__(256, 2) void gemm_h(
        const __half* __restrict__ AHg, const __half* __restrict__ ALg,
        const __half* __restrict__ BHg, const __half* __restrict__ BLg,
        float* CF, __half* CHp, __half* CLp, int rowsPB, int mode)
{
    extern __shared__ uint32_t gsm[];
    const uint32_t sbase = smem_u32(gsm);
    const int tid  = threadIdx.x;
    const int wid  = tid >> 5, lane = tid & 31;
    const int wm   = wid & 3,  wn   = wid >> 2;
    const int g    = lane >> 2, t   = lane & 3;
    const int m0   = blockIdx.y * 128;
    const int n0   = blockIdx.x * 128;
    const int m2   = lane >> 3, r8 = lane & 7;

    float c[2][8][4];
#pragma unroll
    for (int i = 0; i < 2; i++)
#pragma unroll
        for (int j = 0; j < 8; j++)
#pragma unroll
            for (int l = 0; l < 4; l++) c[i][j][l] = 0.f;

    const int lrow = tid >> 1, lc = tid & 1;
    auto ldtile = [&](int kt, int b){
        const char* srcs[4] = {
            (const char*)AHg + (size_t)(m0 + lrow)*2048 + kt*32 + lc*16,
            (const char*)ALg + (size_t)(m0 + lrow)*2048 + kt*32 + lc*16,
            (const char*)BHg + (size_t)(n0 + lrow)*2048 + kt*32 + lc*16,
            (const char*)BLg + (size_t)(n0 + lrow)*2048 + kt*32 + lc*16 };
        const int bases[4] = {G_AH, G_AL, G_BH, G_BL};
#pragma unroll
        for (int i = 0; i < 4; i++)
            cpasync16(sbase + (bases[i] + (b*128 + lrow)*GPW + lc*4)*4, srcs[i]);
        cpcommit();
    };

    ldtile(0, 0);
    ldtile(1, 1);

    for (int kt = 0; kt < 64; kt++) {
        int b = kt % 3;
        if (kt < 63) cpwait<1>(); else cpwait<0>();
        __syncthreads();
        if (kt + 2 < 64) ldtile(kt + 2, (kt + 2) % 3);

        uint32_t aH[2][4], aL[2][4];
#pragma unroll
        for (int mt = 0; mt < 2; mt++) {
            int row = wm*32 + mt*16 + (m2 & 1)*8 + r8;
            uint32_t ad = sbase + (uint32_t)(G_AH + (b*128 + row)*GPW)*4 + (m2 >> 1)*16;
            ldsm4(aH[mt], ad);
            ldsm4(aL[mt], ad + (uint32_t)(G_AL - G_AH)*4);
        }
#pragma unroll
        for (int p = 0; p < 4; p++) {
            int brow = wn*64 + p*16 + ((lane >> 4) & 1)*8 + r8;
            uint32_t bd = sbase + (uint32_t)(G_BH + (b*128 + brow)*GPW)*4 + ((lane >> 3) & 1)*16;
            uint32_t bf[4], bl[4];
            ldsm4(bf, bd);
            ldsm4(bl, bd + (uint32_t)(G_BL - G_BH)*4);
#pragma unroll
            for (int mt = 0; mt < 2; mt++) {
                mma3h(c[mt][2*p],     aH[mt], aL[mt], bf,     bl);
                mma3h(c[mt][2*p + 1], aH[mt], aL[mt], bf + 2, bl + 2);
            }
        }
    }

#pragma unroll
    for (int mt = 0; mt < 2; mt++) {
        int rowg = m0 + wm*32 + mt*16 + g;
#pragma unroll
        for (int nt = 0; nt < 8; nt++) {
            int col = n0 + wn*64 + nt*8 + 2*t;
            float c0 = c[mt][nt][0], c1 = c[mt][nt][1], c2 = c[mt][nt][2], c3 = c[mt][nt][3];
            if (mode == 2) {
                int nn = rowg / rowsPB, r = rowg % rowsPB;
                int hh = col >> 6, ss = col & 63;
                size_t w0 = ((size_t)(nn*HH + hh)*rowsPB + r)*32 + (ss >> 1);
                size_t w1 = w0 + 8*32;
                ((uint32_t*)CHp)[w0] = pack2(c0, c1, false);
                ((uint32_t*)CLp)[w0] = pack2(c0, c1, true);
                ((uint32_t*)CHp)[w1] = pack2(c2, c3, false);
                ((uint32_t*)CLp)[w1] = pack2(c2, c3, true);
            } else if (mode == 1) {
                int nn = rowg / rowsPB, r = rowg % rowsPB;
                int hh = col >> 6, ss = col & 63;
                float* d0 = CF + ((size_t)(nn*HH + hh)*rowsPB + r)*64 + ss;
                float* d1 = CF + ((size_t)(nn*HH + hh)*rowsPB + r + 8)*64 + ss;
                *(float2*)d0 = make_float2(c0, c1);
                *(float2*)d1 = make_float2(c2, c3);
            } else {
                *(float2*)(CF + (size_t)rowg*1024 + col)       = make_float2(c0, c1);
                *(float2*)(CF + (size_t)(rowg + 8)*1024 + col) = make_float2(c2, c3);
            }
        }
    }
}

// ---------------- attention: QT=16, 256 threads, 2 CTAs/SM ----------------
// smem: logits fp32 [16][1044] (66816 B; halves in place after softmax)
//       tiles 32KB: QK hi-only 2-stage [2][128][32w]; V single-stage hi [64][64w] + lo (+4096w)
//       q hi tiles: qcH, qpH each [16][36w]; misc
#define OFF_LOG  0
#define OFF_TILE 66816
#define OFF_Q    (OFF_TILE + 32768)             // 99584
#define OFF_MISC (OFF_Q + 2*16*36*4)            // 104192
#define ATTN_SMEM_BYTES (OFF_MISC + 256)

__global__ __launch_bounds__(256, 2) void attn_kernel(
                            const float* __restrict__ Qp, int NQ,
                            const __half* __restrict__ kcHg,
                            const __half* __restrict__ kpHg,
                            const __half* __restrict__ vtHg, const __half* __restrict__ vtLg,
                            const float* __restrict__ segenc,
                            const int* __restrict__ segmat,
                            const float* __restrict__ mask,
                            const float* __restrict__ cb, const float* __restrict__ pb,
                            const float* __restrict__ sb,
                            const int* __restrict__ tpos,
                            __half* outH, __half* outL)
{
    extern __shared__ char asm_[];
    float* logitsF = (float*)(asm_ + OFF_LOG);
    uint32_t* qw  = (uint32_t*)(asm_ + OFF_Q);        // qcH, qpH each 576 words
    float* seg0 = (float*)(asm_ + OFF_MISC);
    float* seg1 = seg0 + 16;
    int*   qrow = (int*)(seg1 + 16);

    const int n  = blockIdx.z, h = blockIdx.y;
    const int nh = n*HH + h;
    const int q0 = blockIdx.x * QT;
    const int tid = threadIdx.x;
    const int wid = tid >> 5, lane = tid & 31;
    const int g = lane >> 2, t = lane & 3;
    const int m2 = lane >> 3, r8 = lane & 7;
    const uint32_t tbase = smem_u32(asm_ + OFF_TILE);
    const uint32_t qbaseS = smem_u32(qw);
    const uint32_t logb = smem_u32(asm_);

    // ---- QK tile loader: hi only, 2 stages of 16KB; swizzle chunk c ^= r&7 ----
    auto ld_qk = [&](int i, int b){
        const char* sH = (i < 8)
            ? (const char*)kcHg + ((size_t)nh*1024 + (size_t)i*128) * 128
            : (const char*)kpHg + ((size_t)nh*1536 + (size_t)(i-8)*128) * 128;
#pragma unroll
        for (int j = 0; j < 4; j++) {
            int idx = tid + j*256;               // 0..1023
            int row = idx >> 3, c = idx & 7;
            int cc = c ^ (row & 7);
            uint32_t dst = tbase + ((b*128 + row)*32 + cc*4)*4;
            cpasync16(dst, sH + row*128 + c*16);
        }
        cpcommit();
    };
    // ---- V tile loader: single stage; hi at +0, lo at +4096w; swizzle c ^= s&7 ----
    auto ld_vt = [&](int rt){
#pragma unroll
        for (int j = 0; j < 8; j++) {
            int idx = tid + j*256;
            int grp = idx >> 10;
            int c2 = idx & 1023;
            int s = c2 >> 4, c = c2 & 15;
            int cc = c ^ (s & 7);
            uint32_t dst = tbase + (grp*4096 + s*64 + cc*4)*4;
            const char* src = (grp ? (const char*)vtLg : (const char*)vtHg)
                              + ((size_t)nh*64 + s)*2048 + rt*256 + c*16;
            cpasync16(dst, src);
        }
        cpcommit();
    };

    // ---- init: q tiles (hi only); seg dots; qrow ----
    const float* qbase = Qp + ((size_t)nh*NQ + q0)*64;
    {
        int l = tid >> 4, s4 = tid & 15;
        float4 qv = *(const float4*)(qbase + l*64 + s4*4);
        float qa[4] = {qv.x, qv.y, qv.z, qv.w};
        float cbv[4], pbv[4];
#pragma unroll
        for (int i = 0; i < 4; i++) { cbv[i] = cb[h*SS + s4*4 + i]; pbv[i] = pb[h*SS + s4*4 + i]; }
        uint32_t* qcH = qw;
        uint32_t* qpH = qw + 576;
#pragma unroll
        for (int i = 0; i < 2; i++) {
            float a0 = qa[2*i] + cbv[2*i], a1 = qa[2*i+1] + cbv[2*i+1];
            float p0 = qa[2*i] + pbv[2*i], p1 = qa[2*i+1] + pbv[2*i+1];
            qcH[l*36 + s4*2 + i] = pack2(a0, a1, false);
            qpH[l*36 + s4*2 + i] = pack2(p0, p1, false);
        }
    }
    if (tid < QT) qrow[tid] = tpos ? tpos[n*PPQ + q0 + tid] : (q0 + tid);
    if (tid >= 64 && tid < 64 + 2*QT) {
        int i = tid - 64;
        int l = i >> 1, gg = i & 1;
        float acc = 0.f;
        const float* qr = qbase + l*64;
        const float* se = segenc + ((size_t)gg*HH + h)*SS;
        for (int s = 0; s < SS; s++) acc += (qr[s] + sb[h*SS + s]) * se[s];
        if (gg) seg1[l] = acc; else seg0[l] = acc;
    }

    ld_qk(0, 0);
    __syncthreads();

    const int qp0 = qrow[g], qp1 = qrow[g + 8];

    // ---- QK pipeline: 20 tiles, 2-stage, hi-only mma ----
    for (int i = 0; i < 20; i++) {
        int b = i & 1;
        if (i + 1 < 20) { ld_qk(i + 1, (i + 1) & 1); cpwait<1>(); }
        else            { cpwait<0>(); }
        __syncthreads();

        uint32_t qsel = qbaseS + ((i < 8) ? 0u : 576u*4);
        float cres[2][4] = {{0,0,0,0},{0,0,0,0}};
#pragma unroll
        for (int ch = 0; ch < 4; ch++) {
            uint32_t aad = qsel + (uint32_t)(((m2 & 1)*8 + r8)*36)*4 + ch*32 + (m2 >> 1)*16;
            uint32_t aH[4];
            ldsm4(aH, aad);
            int brow = wid*16 + ((lane >> 4) & 1)*8 + r8;
            int bch = (2*ch + ((lane >> 3) & 1)) ^ r8;
            uint32_t bad = tbase + (uint32_t)((b*128 + brow)*32 + bch*4)*4;
            uint32_t bf[4];
            ldsm4(bf, bad);
            mma_h(cres[0], aH, bf);
            mma_h(cres[1], aH, bf + 2);
        }
        if (i < 8) {
#pragma unroll
            for (int j = 0; j < 2; j++) {
                int base = i*128 + wid*16 + j*8 + 2*t;
                logitsF[g*1044 + base]         = cres[j][0];
                logitsF[g*1044 + base + 1]     = cres[j][1];
                logitsF[(g+8)*1044 + base]     = cres[j][2];
                logitsF[(g+8)*1044 + base + 1] = cres[j][3];
            }
        } else {
            int pt = i - 8;
#pragma unroll
            for (int j = 0; j < 2; j++) {
                int pp = pt*128 + wid*16 + j*8 + 2*t;
                int r;
                r = pp     - 512 + qp0; if (r >= 0 && r < RR) logitsF[g*1044 + r]     += cres[j][0];
                r = pp + 1 - 512 + qp0; if (r >= 0 && r < RR) logitsF[g*1044 + r]     += cres[j][1];
                r = pp     - 512 + qp1; if (r >= 0 && r < RR) logitsF[(g+8)*1044 + r] += cres[j][2];
                r = pp + 1 - 512 + qp1; if (r >= 0 && r < RR) logitsF[(g+8)*1044 + r] += cres[j][3];
            }
        }
        __syncthreads();
    }

    // prefetch first V tile under softmax/conversion (single stage buffer is free)
    ld_vt(0);

    // ---- softmax: 16 threads per row ----
    {
        int row = tid >> 4, l16 = tid & 15;
        int qq = qrow[row];
        const float* mrow = mask + ((size_t)n*QQ + qq)*RR;
        const int* srow = segmat + ((size_t)n*QQ + qq)*RR;
        float s1v = seg1[row], s0v = seg0[row];
        float* lrow = logitsF + row*1044;
        float mx = -3.4e38f;
        for (int i = 0; i < 64; i++) {
            int cc = l16 + 16*i;
            float lg = lrow[cc] + (srow[cc] ? s1v : s0v);
            lg = lg * 0.125f + mrow[cc] * (-1e9f);
            lrow[cc] = lg;
            mx = fmaxf(mx, lg);
        }
        for (int o = 8; o; o >>= 1) mx = fmaxf(mx, __shfl_xor_sync(0xffffffffu, mx, o, 16));
        float sum = 0.f;
        for (int i = 0; i < 64; i++) {
            int cc = l16 + 16*i;
            float e = __expf(lrow[cc] - mx);
            lrow[cc] = e;
            sum += e;
        }
        for (int o = 8; o; o >>= 1) sum += __shfl_xor_sync(0xffffffffu, sum, o, 16);
        float inv = __fdividef(1.f, sum);
        for (int i = 0; i < 64; i++) lrow[l16 + 16*i] *= inv;
    }
    __syncthreads();

    // ---- logits fp32 -> halves in place (hi +0, lo +2048 per 4176 B row) ----
    {
        int rsub = tid >> 6;
        int c0 = (tid & 63) * 16;
        for (int p = 0; p < 4; p++) {
            int row = p*4 + rsub;
            const float* src = logitsF + row*1044;
            float v[16];
#pragma unroll
            for (int i = 0; i < 4; i++) {
                float4 f = *(const float4*)(src + c0 + i*4);
                v[4*i] = f.x; v[4*i+1] = f.y; v[4*i+2] = f.z; v[4*i+3] = f.w;
            }
            __syncthreads();
            uint32_t* wh = (uint32_t*)(asm_ + row*4176);
            uint32_t* wl = (uint32_t*)(asm_ + row*4176 + 2048);
#pragma unroll
            for (int i = 0; i < 8; i++) {
                wh[c0/2 + i] = pack2(v[2*i], v[2*i+1], false);
                wl[c0/2 + i] = pack2(v[2*i], v[2*i+1], true);
            }
            __syncthreads();
        }
    }

    // ---- Phase B: out = weights @ V, single-stage V, 3-mma ----
    {
        float ca[4] = {0,0,0,0}, cbn[4] = {0,0,0,0};
        for (int rt = 0; rt < 8; rt++) {
            cpwait<0>();
            __syncthreads();
#pragma unroll
            for (int ch = 0; ch < 8; ch++) {
                int kw = rt*64 + ch*8;
                uint32_t aad = logb + (uint32_t)((m2 & 1)*8 + r8)*4176 + kw*4 + (m2 >> 1)*16;
                uint32_t aH[4], aL[4];
                ldsm4(aH, aad);
                ldsm4(aL, aad + 2048);
                int srow = wid*8 + r8;
                int vch = (2*ch + ((lane >> 3) & 1)) ^ r8;
                uint32_t bad = tbase + (uint32_t)(srow*64 + vch*4)*4;
                uint32_t bH2[2], bL2[2];
                ldsm2(bH2, bad);
                ldsm2(bL2, bad + 4096u*4);
                mma3h((ch & 1) ? cbn : ca, aH, aL, bH2, bL2);
            }
            __syncthreads();
            if (rt + 1 < 8) ld_vt(rt + 1);
        }
#pragma unroll
        for (int l = 0; l < 4; l++) ca[l] += cbn[l];
        size_t w0 = ((size_t)(n*NQ + q0 + g    ))*512 + h*32 + wid*4 + t;
        size_t w1 = ((size_t)(n*NQ + q0 + g + 8))*512 + h*32 + wid*4 + t;
        ((uint32_t*)outH)[w0] = pack2(ca[0], ca[1], false);
        ((uint32_t*)outL)[w0] = pack2(ca[0], ca[1], true);
        ((uint32_t*)outH)[w1] = pack2(ca[2], ca[3], false);
        ((uint32_t*)outL)[w1] = pack2(ca[2], ca[3], true);
    }
}

// -------------------- launch --------------------
extern "C" void kernel_launch(void* const* d_in, const int* in_sizes, int n_in,
                              void* d_out, int out_size)
{
    const float* content = (const float*)d_in[0];
    const float* query   = (const float*)d_in[1];
    const float* posenc  = (const float*)d_in[2];
    const float* segenc  = (const float*)d_in[3];
    const int*   segmat  = (const int*)d_in[4];
    const float* tmap    = (const float*)d_in[5];
    const float* cmask   = (const float*)d_in[6];
    const float* qmask   = (const float*)d_in[7];
    const float* cb      = (const float*)d_in[8];
    const float* pb      = (const float*)d_in[9];
    const float* sb      = (const float*)d_in[10];
    const float* mems    = (const float*)d_in[11];
    const float* Wq      = (const float*)d_in[12];
    const float* Wkc     = (const float*)d_in[13];
    const float* Wv      = (const float*)d_in[14];
    const float* Wkp     = (const float*)d_in[15];
    const float* Wo      = (const float*)d_in[16];
    float* out = (float*)d_out;

    __half *ctxH, *ctxL, *posH, *posL, *conH, *conL, *qryH, *qryL, *wH, *wL;
    __half *kcH, *kcL, *kpH, *kpL, *vtH, *vtL, *acH, *acL, *aqH, *aqL;
    float *pv, *pqc, *pqq;
    int* ptpos;
    cudaGetSymbolAddress((void**)&ctxH, g_ctxH); cudaGetSymbolAddress((void**)&ctxL, g_ctxL);
    cudaGetSymbolAddress((void**)&posH, g_posH); cudaGetSymbolAddress((void**)&posL, g_posL);
    cudaGetSymbolAddress((void**)&conH, g_conH); cudaGetSymbolAddress((void**)&conL, g_conL);
    cudaGetSymbolAddress((void**)&qryH, g_qryH); cudaGetSymbolAddress((void**)&qryL, g_qryL);
    cudaGetSymbolAddress((void**)&wH,   g_wH);   cudaGetSymbolAddress((void**)&wL,   g_wL);
    cudaGetSymbolAddress((void**)&kcH,  g_kcH);  cudaGetSymbolAddress((void**)&kcL,  g_kcL);
    cudaGetSymbolAddress((void**)&kpH,  g_kpH);  cudaGetSymbolAddress((void**)&kpL,  g_kpL);
    cudaGetSymbolAddress((void**)&vtH,  g_vtH);  cudaGetSymbolAddress((void**)&vtL,  g_vtL);
    cudaGetSymbolAddress((void**)&acH,  g_acH);  cudaGetSymbolAddress((void**)&acL,  g_acL);
    cudaGetSymbolAddress((void**)&aqH,  g_aqH);  cudaGetSymbolAddress((void**)&aqL,  g_aqL);
    cudaGetSymbolAddress((void**)&pv,   g_v);
    cudaGetSymbolAddress((void**)&pqc,  g_qc);
    cudaGetSymbolAddress((void**)&pqq,  g_qq);
    cudaGetSymbolAddress((void**)&ptpos, g_tpos);

    cudaFuncSetAttribute(gemm_h, cudaFuncAttributeMaxDynamicSharedMemorySize, GEMM_SMEM);
    cudaFuncSetAttribute(attn_kernel, cudaFuncAttributeMaxDynamicSharedMemorySize, ATTN_SMEM_BYTES);

    // converts
    build_ctx_split<<<4096, 256>>>(mems, content);
    split_k<<<6144, 256>>>(posenc,  posH, posL, BB*RP*HID/4);
    split_k<<<2048, 256>>>(content, conH, conL, BB*QQ*HID/4);
    split_k<<<512,  256>>>(query,   qryH, qryL, BB*PPQ*HID/4);
    dim3 wtb(32, 8), wtg(32, 32);
    wtrans<<<wtg, wtb>>>(Wq,  wH + 0*(size_t)HID*HID, wL + 0*(size_t)HID*HID);
    wtrans<<<wtg, wtb>>>(Wkc, wH + 1*(size_t)HID*HID, wL + 1*(size_t)HID*HID);
    wtrans<<<wtg, wtb>>>(Wv,  wH + 2*(size_t)HID*HID, wL + 2*(size_t)HID*HID);
    wtrans<<<wtg, wtb>>>(Wkp, wH + 3*(size_t)HID*HID, wL + 3*(size_t)HID*HID);
    wtrans<<<wtg, wtb>>>(Wo,  wH + 4*(size_t)HID*HID, wL + 4*(size_t)HID*HID);
    find_tpos<<<1, 512>>>(tmap);

    __half* wq_H = wH + 0*(size_t)HID*HID; __half* wq_L = wL + 0*(size_t)HID*HID;
    __half* wkcH = wH + 1*(size_t)HID*HID; __half* wkcL = wL + 1*(size_t)HID*HID;
    __half* wv_H = wH + 2*(size_t)HID*HID; __half* wv_L = wL + 2*(size_t)HID*HID;
    __half* wkpH = wH + 3*(size_t)HID*HID; __half* wkpL = wL + 3*(size_t)HID*HID;
    __half* wo_H = wH + 4*(size_t)HID*HID; __half* wo_L = wL + 4*(size_t)HID*HID;

    gemm_h<<<dim3(8, 32), 256, GEMM_SMEM>>>(ctxH, ctxL, wkcH, wkcL, nullptr, kcH, kcL, RR,  2);
    gemm_h<<<dim3(8, 32), 256, GEMM_SMEM>>>(ctxH, ctxL, wv_H, wv_L, pv, nullptr, nullptr, RR, 1);
    gemm_h<<<dim3(8, 48), 256, GEMM_SMEM>>>(posH, posL, wkpH, wkpL, nullptr, kpH, kpL, RP,  2);
    gemm_h<<<dim3(8, 16), 256, GEMM_SMEM>>>(conH, conL, wq_H, wq_L, pqc, nullptr, nullptr, QQ, 1);
    gemm_h<<<dim3(8, 4),  256, GEMM_SMEM>>>(qryH, qryL, wq_H, wq_L, pqq, nullptr, nullptr, PPQ, 1);
    vtrans<<<NHDIM*8, 256>>>();

    dim3 gac(QQ/QT, HH, BB);
    attn_kernel<<<gac, 256, ATTN_SMEM_BYTES>>>(pqc, QQ, kcH, kpH, vtH, vtL,
                                               segenc, segmat, cmask, cb, pb, sb, nullptr, acH, acL);
    dim3 gaq(PPQ/QT, HH, BB);
    attn_kernel<<<gaq, 256, ATTN_SMEM_BYTES>>>(pqq, PPQ, kcH, kpH, vtH, vtL,
                                               segenc, segmat, qmask, cb, pb, sb, ptpos, aqH, aqL);

    gemm_h<<<dim3(8, 16), 256, GEMM_SMEM>>>(acH, acL, wo_H, wo_L, out, nullptr, nullptr, 0, 0);
    gemm_h<<<dim3(8, 4),  256, GEMM_SMEM>>>(aqH, aqL, wo_H, wo_L, out + (size_t)BB*QQ*HID, nullptr, nullptr, 0, 0);
}

// round 17
// speedup vs baseline: 1.0035x; 1.0035x over previous
#include <cuda_runtime.h>
#include <cuda_fp16.h>
#include <cstdint>

#define BB  4
#define QQ  512
#define MM  512
#define PPQ 128
#define HID 1024
#define HH  16
#define SS  64
#define RR  1024
#define RP  1536
#define QT  32
#define NHDIM (BB*HH)

// ---------------- global scratch (halves pre-split hi/lo) ----------------
__device__ __align__(16) __half g_ctxH[BB*RR*HID],  g_ctxL[BB*RR*HID];
__device__ __align__(16) __half g_posH[BB*RP*HID],  g_posL[BB*RP*HID];
__device__ __align__(16) __half g_conH[BB*QQ*HID],  g_conL[BB*QQ*HID];
__device__ __align__(16) __half g_qryH[BB*PPQ*HID], g_qryL[BB*PPQ*HID];
__device__ __align__(16) __half g_wH[5*HID*HID],    g_wL[5*HID*HID];
__device__ __align__(16) __half g_kcH[BB*RR*HID],   g_kcL[BB*RR*HID];
__device__ __align__(16) __half g_kpH[BB*RP*HID],   g_kpL[BB*RP*HID];
__device__ __align__(16) __half g_vtH[BB*RR*HID],   g_vtL[BB*RR*HID];
__device__ __align__(16) __half g_acH[BB*QQ*HID],   g_acL[BB*QQ*HID];
__device__ __align__(16) __half g_aqH[BB*PPQ*HID],  g_aqL[BB*PPQ*HID];
__device__ float g_v [BB*RR*HID];
__device__ float g_qc[BB*QQ*HID];
__device__ float g_qq[BB*PPQ*HID];
__device__ int   g_tpos[BB*PPQ];

// ---------------- helpers ----------------
__device__ __forceinline__ uint32_t smem_u32(const void* p){
    uint32_t a;
    asm("{ .reg .u64 t; cvta.to.shared.u64 t, %1; cvt.u32.u64 %0, t; }" : "=r"(a) : "l"(p));
    return a;
}
__device__ __forceinline__ void cpasync16(uint32_t s, const void* g){
    asm volatile("cp.async.cg.shared.global [%0], [%1], 16;" :: "r"(s), "l"(g));
}
__device__ __forceinline__ void cpcommit(){ asm volatile("cp.async.commit_group;" ::: "memory"); }
template<int N> __device__ __forceinline__ void cpwait(){ asm volatile("cp.async.wait_group %0;" :: "n"(N) : "memory"); }

__device__ __forceinline__ void ldsm4(uint32_t* r, uint32_t addr){
    asm volatile("ldmatrix.sync.aligned.m8n8.x4.shared.b16 {%0,%1,%2,%3}, [%4];"
        : "=r"(r[0]),"=r"(r[1]),"=r"(r[2]),"=r"(r[3]) : "r"(addr));
}
__device__ __forceinline__ void ldsm2(uint32_t* r, uint32_t addr){
    asm volatile("ldmatrix.sync.aligned.m8n8.x2.shared.b16 {%0,%1}, [%2];"
        : "=r"(r[0]),"=r"(r[1]) : "r"(addr));
}

__device__ __forceinline__ void split_h(float x, __half& h, __half& l){
    h = __float2half_rn(x);
    l = __float2half_rn(x - __half2float(h));
}
__device__ __forceinline__ uint32_t pack2(float a, float b, bool lo){
    __half ha, la, hb, lb;
    split_h(a, ha, la); split_h(b, hb, lb);
    __half2 v = lo ? __halves2half2(la, lb) : __halves2half2(ha, hb);
    return *(uint32_t*)&v;
}
__device__ __forceinline__ void mma_h(float* c, const uint32_t* a, const uint32_t* b){
    asm volatile("mma.sync.aligned.m16n8k16.row.col.f32.f16.f16.f32 "
        "{%0,%1,%2,%3}, {%4,%5,%6,%7}, {%8,%9}, {%0,%1,%2,%3};"
        : "+f"(c[0]),"+f"(c[1]),"+f"(c[2]),"+f"(c[3])
        : "r"(a[0]),"r"(a[1]),"r"(a[2]),"r"(a[3]), "r"(b[0]),"r"(b[1]));
}
__device__ __forceinline__ void mma3h(float* c, const uint32_t* aH, const uint32_t* aL,
                                      const uint32_t* bH, const uint32_t* bL){
    mma_h(c, aH, bH);
    mma_h(c, aH, bL);
    mma_h(c, aL, bH);
}

// ---------------- converts ----------------
__global__ void build_ctx_split(const float* __restrict__ mems, const float* __restrict__ content)
{
    int idx = blockIdx.x * blockDim.x + threadIdx.x;
    const int total = BB*RR*HID/4;
    if (idx >= total) return;
    int d4  = idx & 255;
    int row = idx >> 8;
    int n = row >> 10, r = row & 1023;
    const float* src = (r < MM) ? (mems + ((size_t)n*MM + r)*HID)
                                : (content + ((size_t)n*QQ + (r-MM))*HID);
    float4 v = ((const float4*)src)[d4];
    uint32_t* wh = (uint32_t*)g_ctxH;
    uint32_t* wl = (uint32_t*)g_ctxL;
    wh[idx*2]   = pack2(v.x, v.y, false);
    wh[idx*2+1] = pack2(v.z, v.w, false);
    wl[idx*2]   = pack2(v.x, v.y, true);
    wl[idx*2+1] = pack2(v.z, v.w, true);
}

__global__ void split_k(const float* __restrict__ src, __half* dstH, __half* dstL, int n4)
{
    int idx = blockIdx.x * blockDim.x + threadIdx.x;
    if (idx >= n4) return;
    float4 v = ((const float4*)src)[idx];
    ((uint32_t*)dstH)[idx*2]   = pack2(v.x, v.y, false);
    ((uint32_t*)dstH)[idx*2+1] = pack2(v.z, v.w, false);
    ((uint32_t*)dstL)[idx*2]   = pack2(v.x, v.y, true);
    ((uint32_t*)dstL)[idx*2+1] = pack2(v.z, v.w, true);
}

// W [k][n] -> WT halves [n][k-pairs]
__global__ void wtrans(const float* __restrict__ W, __half* dstH, __half* dstL)
{
    __shared__ float sm[32][33];
    int n0 = blockIdx.x*32, k0 = blockIdx.y*32;
    int tx = threadIdx.x, ty = threadIdx.y;
#pragma unroll
    for (int i = 0; i < 4; i++)
        sm[ty + 8*i][tx] = W[(size_t)(k0 + ty + 8*i)*1024 + n0 + tx];
    __syncthreads();
    int tid = ty*32 + tx;
    int w = tid & 15;
#pragma unroll
    for (int p = 0; p < 2; p++) {
        int nn = p*16 + (tid >> 4);
        float a = sm[2*w][nn], b = sm[2*w+1][nn];
        size_t o = (size_t)(n0 + nn)*512 + (k0 >> 1) + w;
        ((uint32_t*)dstH)[o] = pack2(a, b, false);
        ((uint32_t*)dstL)[o] = pack2(a, b, true);
    }
}

// g_v fp32 [nh][r][64] -> vt halves [nh][s][r-pairs]
__global__ void vtrans()
{
    __shared__ float vs[128][65];
    int nh = blockIdx.x >> 3, rc = blockIdx.x & 7;
    int tid = threadIdx.x;
    const float* src = g_v + ((size_t)nh*1024 + rc*128)*64;
#pragma unroll
    for (int i = 0; i < 8; i++) {
        int idx = tid + i*256;
        int r = idx >> 4, f4 = idx & 15;
        float4 v = ((const float4*)(src + (size_t)r*64))[f4];
        vs[r][f4*4] = v.x; vs[r][f4*4+1] = v.y; vs[r][f4*4+2] = v.z; vs[r][f4*4+3] = v.w;
    }
    __syncthreads();
#pragma unroll
    for (int i = 0; i < 16; i++) {
        int idx = tid + i*256;
        int s = idx >> 6, w = idx & 63;
        float a = vs[2*w][s], b = vs[2*w+1][s];
        size_t o = ((size_t)nh*64 + s)*512 + rc*64 + w;
        ((uint32_t*)g_vtH)[o] = pack2(a, b, false);
        ((uint32_t*)g_vtL)[o] = pack2(a, b, true);
    }
}

__global__ void find_tpos(const float* __restrict__ tm)
{
    int i = threadIdx.x;
    const float* row = tm + (size_t)i * QQ;
    int q = 0;
    for (int j = 0; j < QQ; j++) if (row[j] > 0.5f) q = j;
    g_tpos[i] = q;
}

// ---------------- half-split GEMM, cp.async 3-stage, ldmatrix frags ----------------
#define GPW 12
#define G_AH 0
#define G_AL (3*128*GPW)
#define G_BH (2*3*128*GPW)
#define G_BL (3*3*128*GPW)
#define GEMM_SMEM (4*3*128*GPW*4)

__global__ __launch_bounds__(256, 2) void gemm_h(
        const __half* __restrict__ AHg, const __half* __restrict__ ALg,
        const __half* __restrict__ BHg, const __half* __restrict__ BLg,
        float* CF, __half* CHp, __half* CLp, int rowsPB, int mode)
{
    extern __shared__ uint32_t gsm[];
    const uint32_t sbase = smem_u32(gsm);
    const int tid  = threadIdx.x;
    const int wid  = tid >> 5, lane = tid & 31;
    const int wm   = wid & 3,  wn   = wid >> 2;
    const int g    = lane >> 2, t   = lane & 3;
    const int m0   = blockIdx.y * 128;
    const int n0   = blockIdx.x * 128;
    const int m2   = lane >> 3, r8 = lane & 7;

    float c[2][8][4];
#pragma unroll
    for (int i = 0; i < 2; i++)
#pragma unroll
        for (int j = 0; j < 8; j++)
#pragma unroll
            for (int l = 0; l < 4; l++) c[i][j][l] = 0.f;

    const int lrow = tid >> 1, lc = tid & 1;
    auto ldtile = [&](int kt, int b){
        const char* srcs[4] = {
            (const char*)AHg + (size_t)(m0 + lrow)*2048 + kt*32 + lc*16,
            (const char*)ALg + (size_t)(m0 + lrow)*2048 + kt*32 + lc*16,
            (const char*)BHg + (size_t)(n0 + lrow)*2048 + kt*32 + lc*16,
            (const char*)BLg + (size_t)(n0 + lrow)*2048 + kt*32 + lc*16 };
        const int bases[4] = {G_AH, G_AL, G_BH, G_BL};
#pragma unroll
        for (int i = 0; i < 4; i++)
            cpasync16(sbase + (bases[i] + (b*128 + lrow)*GPW + lc*4)*4, srcs[i]);
        cpcommit();
    };

    ldtile(0, 0);
    ldtile(1, 1);

    for (int kt = 0; kt < 64; kt++) {
        int b = kt % 3;
        if (kt < 63) cpwait<1>(); else cpwait<0>();
        __syncthreads();
        if (kt + 2 < 64) ldtile(kt + 2, (kt + 2) % 3);

        uint32_t aH[2][4], aL[2][4];
#pragma unroll
        for (int mt = 0; mt < 2; mt++) {
            int row = wm*32 + mt*16 + (m2 & 1)*8 + r8;
            uint32_t ad = sbase + (uint32_t)(G_AH + (b*128 + row)*GPW)*4 + (m2 >> 1)*16;
            ldsm4(aH[mt], ad);
            ldsm4(aL[mt], ad + (uint32_t)(G_AL - G_AH)*4);
        }
#pragma unroll
        for (int p = 0; p < 4; p++) {
            int brow = wn*64 + p*16 + ((lane >> 4) & 1)*8 + r8;
            uint32_t bd = sbase + (uint32_t)(G_BH + (b*128 + brow)*GPW)*4 + ((lane >> 3) & 1)*16;
            uint32_t bf[4], bl[4];
            ldsm4(bf, bd);
            ldsm4(bl, bd + (uint32_t)(G_BL - G_BH)*4);
#pragma unroll
            for (int mt = 0; mt < 2; mt++) {
                mma3h(c[mt][2*p],     aH[mt], aL[mt], bf,     bl);
                mma3h(c[mt][2*p + 1], aH[mt], aL[mt], bf + 2, bl + 2);
            }
        }
    }

#pragma unroll
    for (int mt = 0; mt < 2; mt++) {
        int rowg = m0 + wm*32 + mt*16 + g;
#pragma unroll
        for (int nt = 0; nt < 8; nt++) {
            int col = n0 + wn*64 + nt*8 + 2*t;
            float c0 = c[mt][nt][0], c1 = c[mt][nt][1], c2 = c[mt][nt][2], c3 = c[mt][nt][3];
            if (mode == 2) {
                int nn = rowg / rowsPB, r = rowg % rowsPB;
                int hh = col >> 6, ss = col & 63;
                size_t w0 = ((size_t)(nn*HH + hh)*rowsPB + r)*32 + (ss >> 1);
                size_t w1 = w0 + 8*32;
                ((uint32_t*)CHp)[w0] = pack2(c0, c1, false);
                ((uint32_t*)CLp)[w0] = pack2(c0, c1, true);
                ((uint32_t*)CHp)[w1] = pack2(c2, c3, false);
                ((uint32_t*)CLp)[w1] = pack2(c2, c3, true);
            } else if (mode == 1) {
                int nn = rowg / rowsPB, r = rowg % rowsPB;
                int hh = col >> 6, ss = col & 63;
                float* d0 = CF + ((size_t)(nn*HH + hh)*rowsPB + r)*64 + ss;
                float* d1 = CF + ((size_t)(nn*HH + hh)*rowsPB + r + 8)*64 + ss;
                *(float2*)d0 = make_float2(c0, c1);
                *(float2*)d1 = make_float2(c2, c3);
            } else {
                *(float2*)(CF + (size_t)rowg*1024 + col)       = make_float2(c0, c1);
                *(float2*)(CF + (size_t)(rowg + 8)*1024 + col) = make_float2(c2, c3);
            }
        }
    }
}

// ---------------- attention: QT=32, 512 thr, causal tile skipping ----------------
#define OFF_LOG  0
#define OFF_TILE (32*1044*4)                    // 133632
#define OFF_Q    (OFF_TILE + 2*2*128*32*4)      // 199168
#define OFF_MISC (OFF_Q + 4*32*36*4)            // 217600
#define ATTN_SMEM_BYTES (OFF_MISC + 384)

__global__ __launch_bounds__(512) void attn_kernel(
                            const float* __restrict__ Qp, int NQ,
                            const __half* __restrict__ kcHg,
                            const __half* __restrict__ kpHg,
                            const __half* __restrict__ vtHg, const __half* __restrict__ vtLg,
                            const float* __restrict__ segenc,
                            const int* __restrict__ segmat,
                            const float* __restrict__ mask,
                            const float* __restrict__ cb, const float* __restrict__ pb,
                            const float* __restrict__ sb,
                            const int* __restrict__ tpos,
                            __half* outH, __half* outL)
{
    extern __shared__ char asm_[];
    float* logitsF = (float*)(asm_ + OFF_LOG);
    uint32_t* qw  = (uint32_t*)(asm_ + OFF_Q);
    float* seg0 = (float*)(asm_ + OFF_MISC);
    float* seg1 = seg0 + 32;
    int*   qrow = (int*)(seg1 + 32);

    const int n  = blockIdx.z, h = blockIdx.y;
    const int nh = n*HH + h;
    const int q0 = blockIdx.x * QT;
    const int tid = threadIdx.x;
    const int wid = tid >> 5, lane = tid & 31;
    const int g = lane >> 2, t = lane & 3;
    const int m2 = lane >> 3, r8 = lane & 7;
    const int wq = wid >> 3;
    const int wr = wid & 7;
    const uint32_t tbase = smem_u32(asm_ + OFF_TILE);
    const uint32_t qbaseS = smem_u32(qw);
    const uint32_t logb = smem_u32(asm_);

    // ---- QK tile loader: hi only; swizzle chunk c ^= r&7 ----
    auto ld_qk = [&](int i, int b){
        const char* sH = (i < 8)
            ? (const char*)kcHg + ((size_t)nh*1024 + (size_t)i*128) * 128
            : (const char*)kpHg + ((size_t)nh*1536 + (size_t)(i-8)*128) * 128;
#pragma unroll
        for (int j = 0; j < 2; j++) {
            int idx = tid + j*512;
            int row = idx >> 3, c = idx & 7;
            int cc = c ^ (row & 7);
            uint32_t dst = tbase + ((b*128 + row)*32 + cc*4)*4;
            cpasync16(dst, sH + row*128 + c*16);
        }
        cpcommit();
    };
    // ---- V tile loader: hi+lo; swizzle c ^= s&7 ----
    auto ld_vt = [&](int rt, int b){
#pragma unroll
        for (int j = 0; j < 4; j++) {
            int idx = tid + j*512;
            int grp = idx >> 10;
            int c2 = idx & 1023;
            int s = c2 >> 4, c = c2 & 15;
            int cc = c ^ (s & 7);
            uint32_t dst = tbase + (grp*8192 + (b*64 + s)*64 + cc*4)*4;
            const char* src = (grp ? (const char*)vtLg : (const char*)vtHg)
                              + ((size_t)nh*64 + s)*2048 + rt*256 + c*16;
            cpasync16(dst, src);
        }
        cpcommit();
    };

    // ---- init: q tiles (hi only); seg dots; qrow ----
    const float* qbase = Qp + ((size_t)nh*NQ + q0)*64;
    {
        int l = tid >> 4, s4 = tid & 15;
        float4 qv = *(const float4*)(qbase + l*64 + s4*4);
        float qa[4] = {qv.x, qv.y, qv.z, qv.w};
        float cbv[4], pbv[4];
#pragma unroll
        for (int i = 0; i < 4; i++) { cbv[i] = cb[h*SS + s4*4 + i]; pbv[i] = pb[h*SS + s4*4 + i]; }
        uint32_t* qcH = qw;
        uint32_t* qpH = qw + 2304;
#pragma unroll
        for (int i = 0; i < 2; i++) {
            float a0 = qa[2*i] + cbv[2*i], a1 = qa[2*i+1] + cbv[2*i+1];
            float p0 = qa[2*i] + pbv[2*i], p1 = qa[2*i+1] + pbv[2*i+1];
            qcH[l*36 + s4*2 + i] = pack2(a0, a1, false);
            qpH[l*36 + s4*2 + i] = pack2(p0, p1, false);
        }
    }
    if (tid < QT) qrow[tid] = tpos ? tpos[n*PPQ + q0 + tid] : (q0 + tid);
    if (tid >= 64 && tid < 64 + 2*QT) {
        int i = tid - 64;
        int l = i >> 1, gg = i & 1;
        float acc = 0.f;
        const float* qr = qbase + l*64;
        const float* se = segenc + ((size_t)gg*HH + h)*SS;
        for (int s = 0; s < SS; s++) acc += (qr[s] + sb[h*SS + s]) * se[s];
        if (gg) seg1[l] = acc; else seg0[l] = acc;
    }

    ld_qk(0, 0);
    __syncthreads();

    // ---- causal tile bounds (uniform across CTA) ----
    int qmn, qmx;
    if (tpos) {
        qmn = 1 << 30; qmx = 0;
#pragma unroll
        for (int k = 0; k < QT; k++) { int v = qrow[k]; qmn = min(qmn, v); qmx = max(qmx, v); }
    } else { qmn = q0; qmx = q0 + QT - 1; }
    const int rmaxI = min(RR - 1, qmx + 512);
    const int nrt = (rmaxI >> 7) + 1;                      // content/AV tiles needed
    const int ptlo = (512 - qmx) >> 7;                     // first needed position tile
    const int pthi = min(11, (rmaxI + 512 - qmn) >> 7);    // last needed position tile
    const int L = nrt + (pthi - ptlo + 1);
    auto tl = [&](int j){ return (j < nrt) ? j : (8 + ptlo + (j - nrt)); };

    const int qp0 = qrow[wq*16 + g], qp1 = qrow[wq*16 + g + 8];

    // ---- QK pipeline over needed tiles only ----
    for (int j = 0; j < L; j++) {
        int i = tl(j);
        int b = j & 1;
        if (j + 1 < L) { ld_qk(tl(j + 1), (j + 1) & 1); cpwait<1>(); }
        else           { cpwait<0>(); }
        __syncthreads();

        uint32_t qsel = qbaseS + ((i < 8) ? 0u : 2304u*4);
        float cres[2][4] = {{0,0,0,0},{0,0,0,0}};
#pragma unroll
        for (int ch = 0; ch < 4; ch++) {
            uint32_t aad = qsel + (uint32_t)((wq*16 + (m2 & 1)*8 + r8)*36)*4 + ch*32 + (m2 >> 1)*16;
            uint32_t aH[4];
            ldsm4(aH, aad);
            int brow = wr*16 + ((lane >> 4) & 1)*8 + r8;
            int bch = (2*ch + ((lane >> 3) & 1)) ^ r8;
            uint32_t bad = tbase + (uint32_t)((b*128 + brow)*32 + bch*4)*4;
            uint32_t bf[4];
            ldsm4(bf, bad);
            mma_h(cres[0], aH, bf);
            mma_h(cres[1], aH, bf + 2);
        }
        if (i < 8) {
#pragma unroll
            for (int jj = 0; jj < 2; jj++) {
                int base = i*128 + wr*16 + jj*8 + 2*t;
                logitsF[(wq*16 + g    )*1044 + base]     = cres[jj][0];
                logitsF[(wq*16 + g    )*1044 + base + 1] = cres[jj][1];
                logitsF[(wq*16 + g + 8)*1044 + base]     = cres[jj][2];
                logitsF[(wq*16 + g + 8)*1044 + base + 1] = cres[jj][3];
            }
        } else {
            int pt = i - 8;
#pragma unroll
            for (int jj = 0; jj < 2; jj++) {
                int pp = pt*128 + wr*16 + jj*8 + 2*t;
                int r;
                r = pp     - 512 + qp0; if (r >= 0 && r < RR) logitsF[(wq*16 + g    )*1044 + r] += cres[jj][0];
                r = pp + 1 - 512 + qp0; if (r >= 0 && r < RR) logitsF[(wq*16 + g    )*1044 + r] += cres[jj][1];
                r = pp     - 512 + qp1; if (r >= 0 && r < RR) logitsF[(wq*16 + g + 8)*1044 + r] += cres[jj][2];
                r = pp + 1 - 512 + qp1; if (r >= 0 && r < RR) logitsF[(wq*16 + g + 8)*1044 + r] += cres[jj][3];
            }
        }
        __syncthreads();
    }

    // prefetch first V tile under softmax/conversion
    ld_vt(0, 0);

    // ---- softmax (16 thr/row); explicit zero beyond causal limit ----
    {
        int row = tid >> 4, l16 = tid & 15;
        int qq = qrow[row];
        int rlim = min(RR - 1, qq + 512);                  // inclusive causal bound
        const float* mrow = mask + ((size_t)n*QQ + qq)*RR;
        const int* srow = segmat + ((size_t)n*QQ + qq)*RR;
        float s1v = seg1[row], s0v = seg0[row];
        float* lrow = logitsF + row*1044;
        float mx = -3.4e38f;
        for (int i = 0; i < 64; i++) {
            int cc = l16 + 16*i;
            if (cc <= rlim) {
                float lg = lrow[cc] + (srow[cc] ? s1v : s0v);
                lg = lg * 0.125f + mrow[cc] * (-1e9f);
                lrow[cc] = lg;
                mx = fmaxf(mx, lg);
            } else {
                lrow[cc] = -3.4e38f;
            }
        }
        for (int o = 8; o; o >>= 1) mx = fmaxf(mx, __shfl_xor_sync(0xffffffffu, mx, o, 16));
        float sum = 0.f;
        for (int i = 0; i < 64; i++) {
            int cc = l16 + 16*i;
            float e;
            if (cc <= rlim) { e = __expf(lrow[cc] - mx); sum += e; }
            else e = 0.f;
            lrow[cc] = e;
        }
        for (int o = 8; o; o >>= 1) sum += __shfl_xor_sync(0xffffffffu, sum, o, 16);
        float inv = __fdividef(1.f, sum);
        for (int i = 0; i < 64; i++) {
            int cc = l16 + 16*i;
            if (cc <= rlim) lrow[cc] *= inv;
        }
    }
    __syncthreads();

    // ---- logits fp32 -> halves in place (hi +0, lo +2048 per 4176 B row) ----
    {
        int rsub = tid >> 6;
        int c0 = (tid & 63) * 16;
        for (int p = 0; p < 4; p++) {
            int row = p*8 + rsub;
            const float* src = logitsF + row*1044;
            float v[16];
#pragma unroll
            for (int i = 0; i < 4; i++) {
                float4 f = *(const float4*)(src + c0 + i*4);
                v[4*i] = f.x; v[4*i+1] = f.y; v[4*i+2] = f.z; v[4*i+3] = f.w;
            }
            __syncthreads();
            uint32_t* wh = (uint32_t*)(asm_ + row*4176);
            uint32_t* wl = (uint32_t*)(asm_ + row*4176 + 2048);
#pragma unroll
            for (int i = 0; i < 8; i++) {
                wh[c0/2 + i] = pack2(v[2*i], v[2*i+1], false);
                wl[c0/2 + i] = pack2(v[2*i], v[2*i+1], true);
            }
            __syncthreads();
        }
    }

    // ---- Phase B: out = weights @ V over nrt tiles, 2-stage, 3-mma ----
    {
        float ca[4] = {0,0,0,0}, cbn[4] = {0,0,0,0};
        for (int rt = 0; rt < nrt; rt++) {
            int b = rt & 1;
            if (rt + 1 < nrt) { ld_vt(rt + 1, (rt + 1) & 1); cpwait<1>(); }
            else              { cpwait<0>(); }
            __syncthreads();
#pragma unroll
            for (int ch = 0; ch < 8; ch++) {
                int kw = rt*64 + ch*8;
                uint32_t aad = logb + (uint32_t)((wq*16 + (m2 & 1)*8 + r8)*4176) + kw*4 + (m2 >> 1)*16;
                uint32_t aH[4], aL[4];
                ldsm4(aH, aad);
                ldsm4(aL, aad + 2048);
                int srow = wr*8 + r8;
                int vch = (2*ch + ((lane >> 3) & 1)) ^ r8;
                uint32_t bad = tbase + (uint32_t)((b*64 + srow)*64 + vch*4)*4;
                uint32_t bH2[2], bL2[2];
                ldsm2(bH2, bad);
                ldsm2(bL2, bad + 8192u*4);
                mma3h((ch & 1) ? cbn : ca, aH, aL, bH2, bL2);
            }
            __syncthreads();
        }
#pragma unroll
        for (int l = 0; l < 4; l++) ca[l] += cbn[l];
        size_t w0 = ((size_t)(n*NQ + q0 + wq*16 + g    ))*512 + h*32 + wr*4 + t;
        size_t w1 = ((size_t)(n*NQ + q0 + wq*16 + g + 8))*512 + h*32 + wr*4 + t;
        ((uint32_t*)outH)[w0] = pack2(ca[0], ca[1], false);
        ((uint32_t*)outL)[w0] = pack2(ca[0], ca[1], true);
        ((uint32_t*)outH)[w1] = pack2(ca[2], ca[3], false);
        ((uint32_t*)outL)[w1] = pack2(ca[2], ca[3], true);
    }
}

// -------------------- launch --------------------
extern "C" void kernel_launch(void* const* d_in, const int* in_sizes, int n_in,
                              void* d_out, int out_size)
{
    const float* content = (const float*)d_in[0];
    const float* query   = (const float*)d_in[1];
    const float* posenc  = (const float*)d_in[2];
    const float* segenc  = (const float*)d_in[3];
    const int*   segmat  = (const int*)d_in[4];
    const float* tmap    = (const float*)d_in[5];
    const float* cmask   = (const float*)d_in[6];
    const float* qmask   = (const float*)d_in[7];
    const float* cb      = (const float*)d_in[8];
    const float* pb      = (const float*)d_in[9];
    const float* sb      = (const float*)d_in[10];
    const float* mems    = (const float*)d_in[11];
    const float* Wq      = (const float*)d_in[12];
    const float* Wkc     = (const float*)d_in[13];
    const float* Wv      = (const float*)d_in[14];
    const float* Wkp     = (const float*)d_in[15];
    const float* Wo      = (const float*)d_in[16];
    float* out = (float*)d_out;

    __half *ctxH, *ctxL, *posH, *posL, *conH, *conL, *qryH, *qryL, *wH, *wL;
    __half *kcH, *kcL, *kpH, *kpL, *vtH, *vtL, *acH, *acL, *aqH, *aqL;
    float *pv, *pqc, *pqq;
    int* ptpos;
    cudaGetSymbolAddress((void**)&ctxH, g_ctxH); cudaGetSymbolAddress((void**)&ctxL, g_ctxL);
    cudaGetSymbolAddress((void**)&posH, g_posH); cudaGetSymbolAddress((void**)&posL, g_posL);
    cudaGetSymbolAddress((void**)&conH, g_conH); cudaGetSymbolAddress((void**)&conL, g_conL);
    cudaGetSymbolAddress((void**)&qryH, g_qryH); cudaGetSymbolAddress((void**)&qryL, g_qryL);
    cudaGetSymbolAddress((void**)&wH,   g_wH);   cudaGetSymbolAddress((void**)&wL,   g_wL);
    cudaGetSymbolAddress((void**)&kcH,  g_kcH);  cudaGetSymbolAddress((void**)&kcL,  g_kcL);
    cudaGetSymbolAddress((void**)&kpH,  g_kpH);  cudaGetSymbolAddress((void**)&kpL,  g_kpL);
    cudaGetSymbolAddress((void**)&vtH,  g_vtH);  cudaGetSymbolAddress((void**)&vtL,  g_vtL);
    cudaGetSymbolAddress((void**)&acH,  g_acH);  cudaGetSymbolAddress((void**)&acL,  g_acL);
    cudaGetSymbolAddress((void**)&aqH,  g_aqH);  cudaGetSymbolAddress((void**)&aqL,  g_aqL);
    cudaGetSymbolAddress((void**)&pv,   g_v);
    cudaGetSymbolAddress((void**)&pqc,  g_qc);
    cudaGetSymbolAddress((void**)&pqq,  g_qq);
    cudaGetSymbolAddress((void**)&ptpos, g_tpos);

    cudaFuncSetAttribute(gemm_h, cudaFuncAttributeMaxDynamicSharedMemorySize, GEMM_SMEM);
    cudaFuncSetAttribute(attn_kernel, cudaFuncAttributeMaxDynamicSharedMemorySize, ATTN_SMEM_BYTES);

    // converts
    build_ctx_split<<<4096, 256>>>(mems, content);
    split_k<<<6144, 256>>>(posenc,  posH, posL, BB*RP*HID/4);
    split_k<<<2048, 256>>>(content, conH, conL, BB*QQ*HID/4);
    split_k<<<512,  256>>>(query,   qryH, qryL, BB*PPQ*HID/4);
    dim3 wtb(32, 8), wtg(32, 32);
    wtrans<<<wtg, wtb>>>(Wq,  wH + 0*(size_t)HID*HID, wL + 0*(size_t)HID*HID);
    wtrans<<<wtg, wtb>>>(Wkc, wH + 1*(size_t)HID*HID, wL + 1*(size_t)HID*HID);
    wtrans<<<wtg, wtb>>>(Wv,  wH + 2*(size_t)HID*HID, wL + 2*(size_t)HID*HID);
    wtrans<<<wtg, wtb>>>(Wkp, wH + 3*(size_t)HID*HID, wL + 3*(size_t)HID*HID);
    wtrans<<<wtg, wtb>>>(Wo,  wH + 4*(size_t)HID*HID, wL + 4*(size_t)HID*HID);
    find_tpos<<<1, 512>>>(tmap);

    __half* wq_H = wH + 0*(size_t)HID*HID; __half* wq_L = wL + 0*(size_t)HID*HID;
    __half* wkcH = wH + 1*(size_t)HID*HID; __half* wkcL = wL + 1*(size_t)HID*HID;
    __half* wv_H = wH + 2*(size_t)HID*HID; __half* wv_L = wL + 2*(size_t)HID*HID;
    __half* wkpH = wH + 3*(size_t)HID*HID; __half* wkpL = wL + 3*(size_t)HID*HID;
    __half* wo_H = wH + 4*(size_t)HID*HID; __half* wo_L = wL + 4*(size_t)HID*HID;

    gemm_h<<<dim3(8, 32), 256, GEMM_SMEM>>>(ctxH, ctxL, wkcH, wkcL, nullptr, kcH, kcL, RR,  2);
    gemm_h<<<dim3(8, 32), 256, GEMM_SMEM>>>(ctxH, ctxL, wv_H, wv_L, pv, nullptr, nullptr, RR, 1);
    gemm_h<<<dim3(8, 48), 256, GEMM_SMEM>>>(posH, posL, wkpH, wkpL, nullptr, kpH, kpL, RP,  2);
    gemm_h<<<dim3(8, 16), 256, GEMM_SMEM>>>(conH, conL, wq_H, wq_L, pqc, nullptr, nullptr, QQ, 1);
    gemm_h<<<dim3(8, 4),  256, GEMM_SMEM>>>(qryH, qryL, wq_H, wq_L, pqq, nullptr, nullptr, PPQ, 1);
    vtrans<<<NHDIM*8, 256>>>();

    dim3 gac(QQ/QT, HH, BB);
    attn_kernel<<<gac, 512, ATTN_SMEM_BYTES>>>(pqc, QQ, kcH, kpH, vtH, vtL,
                                               segenc, segmat, cmask, cb, pb, sb, nullptr, acH, acL);
    dim3 gaq(PPQ/QT, HH, BB);
    attn_kernel<<<gaq, 512, ATTN_SMEM_BYTES>>>(pqq, PPQ, kcH, kpH, vtH, vtL,
                                               segenc, segmat, qmask, cb, pb, sb, ptpos, aqH, aqL);

    gemm_h<<<dim3(8, 16), 256, GEMM_SMEM>>>(acH, acL, wo_H, wo_L, out, nullptr, nullptr, 0, 0);
    gemm_h<<<dim3(8, 4),  256, GEMM_SMEM>>>(aqH, aqL, wo_H, wo_L, out + (size_t)BB*QQ*HID, nullptr, nullptr, 0, 0);
}